// round 4
// baseline (speedup 1.0000x reference)
#include <cuda_runtime.h>

#define NN 256      // batch
#define PP 128      // points per polygon (= segments)
#define TPB 1024
#define RPB 2       // rows per block
#define NB  (NN / RPB)    // 128 blocks -> single wave on 148 SMs
#define SCH (PP / 4)      // 32 segments per h-chunk
#define PCH (PP / 4)      // 32 preds per h-chunk

__device__ float4 g_part[NN];
__device__ unsigned int g_cnt = 0;

__device__ __forceinline__ float smooth_l1(float p, float t) {
    float d = fabsf(p - t);
    return d < 0.25f ? 2.0f * d * d : d - 0.125f;   // BETA = 0.25
}

__global__ __launch_bounds__(TPB) void dm_fused(
    const float* __restrict__ pred_c,
    const float* __restrict__ pred_o,
    const float* __restrict__ gt_c,
    const float* __restrict__ gt_k,
    const int*   __restrict__ gt_m,
    float*       __restrict__ out)
{
    // per-row segment tables: A=(e0,f0,g0,g1), B=(de,df,g2,-0.5/g2)
    // score(p,k) = alpha + beta*k + gamma*k^2 (convex), k* closed-form
    __shared__ float4 s_tA[RPB][PP], s_tB[RPB][PP];
    __shared__ float4 s_pt[RPB][PP];            // pred score table
    __shared__ float2 s_pred[RPB][PP], s_po[RPB][PP], s_gt[RPB][PP], s_gk[RPB][PP];
    __shared__ float  s_bs[RPB][4 * PP];
    __shared__ float  s_bi[RPB][4 * PP];        // packed float index 16*sg + k
    __shared__ float  s_b2[RPB][4 * PP];
    __shared__ int    s_j2[RPB][4 * PP];
    __shared__ float  s_red[4][32];
    __shared__ int    s_last;

    const int n0 = blockIdx.x * RPB;
    const int t  = threadIdx.x;
    const int r  = t >> 9;          // row within block (0/1)
    const int tr = t & 511;
    const int p  = tr & (PP - 1);
    const int h  = tr >> 7;         // chunk 0..3

    // ---- load: 256 threads, one (row, point) each ----
    if (t < RPB * PP) {
        const int rw = t >> 7, q = t & (PP - 1);
        const size_t off = (size_t)(n0 + rw) * PP;
        s_pred[rw][q] = reinterpret_cast<const float2*>(pred_c)[off + q];
        s_po[rw][q]   = reinterpret_cast<const float2*>(pred_o)[off + q];
        s_gt[rw][q]   = reinterpret_cast<const float2*>(gt_c)[off + q];
        s_gk[rw][q]   = reinterpret_cast<const float2*>(gt_k)[off + q];
    }
    __syncthreads();

    // ---- tables: 256 threads ----
    if (t < RPB * PP) {
        const int rw = t >> 7, q = t & (PP - 1);
        float2 a = s_gt[rw][q];
        float2 b = s_gt[rw][(q + PP - 1) & (PP - 1)];     // k=0 target is b
        float dx = (a.x - b.x) * 0.1f;
        float dy = (a.y - b.y) * 0.1f;
        float g2 = dx * dx + dy * dy;
        float inv = (g2 > 0.0f) ? (-0.5f / g2) : 0.0f;
        s_tA[rw][q] = make_float4(-2.0f * b.x, -2.0f * b.y,
                                  b.x * b.x + b.y * b.y,
                                  2.0f * (b.x * dx + b.y * dy));
        s_tB[rw][q] = make_float4(-2.0f * dx, -2.0f * dy, g2, inv);
        float2 pr = s_pred[rw][q];
        s_pt[rw][q] = make_float4(-2.0f * pr.x, -2.0f * pr.y,
                                  pr.x * pr.x + pr.y * pr.y, 0.0f);
    }
    __syncthreads();

    // ---- item 1: chunk h of segments, closed-form best k ----
    const float px = s_pred[r][p].x, py = s_pred[r][p].y;
    {
        float val[4]; float bif[4];
        #pragma unroll
        for (int u = 0; u < 4; ++u) { val[u] = 3.4e38f; bif[u] = 0.0f; }
        const int base = h * SCH;
        for (int j = 0; j < SCH; j += 4) {
            #pragma unroll
            for (int u = 0; u < 4; ++u) {
                const int sg = base + j + u;
                float4 A = s_tA[r][sg];
                float4 B = s_tB[r][sg];
                float alpha = fmaf(px, A.x, fmaf(py, A.y, A.z));
                float beta  = fmaf(px, B.x, fmaf(py, B.y, A.w));
                float kf = beta * B.w;                      // vertex
                kf = fminf(fmaxf(kf, 0.0f), 9.0f);
                kf = rintf(kf);
                float v = fmaf(kf, fmaf(kf, B.z, beta), alpha);
                float bi = kf + (float)(16 * sg);
                if (v < val[u]) { val[u] = v; bif[u] = bi; }
            }
        }
        float bs = val[0]; float bi = bif[0];
        #pragma unroll
        for (int u = 1; u < 4; ++u)
            if (val[u] < bs || (val[u] == bs && bif[u] < bi)) { bs = val[u]; bi = bif[u]; }
        s_bs[r][tr] = bs; s_bi[r][tr] = bi;
    }

    // ---- item 2: chunk h of preds for key point p ----
    {
        const float kx = s_gk[r][p].x, ky = s_gk[r][p].y;
        float b2[4]; int j2[4];
        #pragma unroll
        for (int u = 0; u < 4; ++u) { b2[u] = 3.4e38f; j2[u] = 0; }
        const int pb = h * PCH;
        for (int j = 0; j < PCH; j += 4) {
            #pragma unroll
            for (int u = 0; u < 4; ++u) {
                float4 E = s_pt[r][pb + j + u];
                float d = fmaf(kx, E.x, fmaf(ky, E.y, E.z));
                if (d < b2[u]) { b2[u] = d; j2[u] = pb + j + u; }
            }
        }
        float bs = b2[0]; int bi = j2[0];
        #pragma unroll
        for (int u = 1; u < 4; ++u)
            if (b2[u] < bs || (b2[u] == bs && j2[u] < bi)) { bs = b2[u]; bi = j2[u]; }
        s_b2[r][tr] = bs; s_j2[r][tr] = bi;
    }
    __syncthreads();

    // ---- combine across chunks + per-point losses (256 threads active) ----
    float s1 = 0.0f, c1 = 0.0f, s2 = 0.0f, c2 = 0.0f;
    if (tr < PP) {
        // item 1
        float bs = s_bs[r][tr]; float bif = s_bi[r][tr];
        #pragma unroll
        for (int hh = 1; hh < 4; ++hh) {
            float s = s_bs[r][hh * PP + tr]; float b = s_bi[r][hh * PP + tr];
            if (s < bs || (s == bs && b < bif)) { bs = s; bif = b; }
        }
        {
            int bi = (int)bif;
            int sg = bi >> 4;
            float kf = (float)(bi & 15);
            float4 A = s_tA[r][sg];
            float4 B = s_tB[r][sg];
            float tx = -0.5f * fmaf(kf, B.x, A.x);
            float ty = -0.5f * fmaf(kf, B.y, A.y);
            float mpx = s_pred[r][tr].x, mpy = s_pred[r][tr].y;
            float dxx = mpx - tx, dyy = mpy - ty;
            float d2 = dxx * dxx + dyy * dyy;
            if (d2 <= 1.0e6f) {
                float2 mo = s_po[r][tr];
                float ox = (tx - mpx) * 0.25f;
                float oy = (ty - mpy) * 0.25f;
                s1 = smooth_l1(mo.x, ox) + smooth_l1(mo.y, oy);
                c1 = 1.0f;
            }
        }
        // item 2
        float b2m = s_b2[r][tr]; int j2m = s_j2[r][tr];
        #pragma unroll
        for (int hh = 1; hh < 4; ++hh) {
            float s = s_b2[r][hh * PP + tr]; int j = s_j2[r][hh * PP + tr];
            if (s < b2m || (s == b2m && j < j2m)) { b2m = s; j2m = j; }
        }
        int mk = gt_m[(size_t)(n0 + r) * PP + tr];
        float2 kk = s_gk[r][tr];
        float kk2 = kk.x * kk.x + kk.y * kk.y;              // restore dist^2
        if (mk && (b2m + kk2) <= 1.0e6f) {
            float2 pg = s_pred[r][j2m];
            float2 og = s_po[r][j2m];
            float ox = (kk.x - pg.x) * 0.25f;
            float oy = (kk.y - pg.y) * 0.25f;
            s2 = smooth_l1(og.x, ox) + smooth_l1(og.y, oy);
            c2 = 1.0f;
        }
    }

    // ---- deterministic reduction: warps 0-15 = row 0, 16-31 = row 1 ----
    #pragma unroll
    for (int o = 16; o > 0; o >>= 1) {
        s1 += __shfl_down_sync(0xffffffffu, s1, o);
        c1 += __shfl_down_sync(0xffffffffu, c1, o);
        s2 += __shfl_down_sync(0xffffffffu, s2, o);
        c2 += __shfl_down_sync(0xffffffffu, c2, o);
    }
    const int w = t >> 5, l = t & 31;
    if (l == 0) {
        s_red[0][w] = s1; s_red[1][w] = c1;
        s_red[2][w] = s2; s_red[3][w] = c2;
    }
    __syncthreads();
    if (t == 0) {
        #pragma unroll
        for (int rr = 0; rr < RPB; ++rr) {
            float a0 = 0.f, a1 = 0.f, a2 = 0.f, a3 = 0.f;
            #pragma unroll
            for (int i = 0; i < 16; ++i) {
                a0 += s_red[0][rr * 16 + i]; a1 += s_red[1][rr * 16 + i];
                a2 += s_red[2][rr * 16 + i]; a3 += s_red[3][rr * 16 + i];
            }
            g_part[n0 + rr] = make_float4(a0, a1, a2, a3);
        }
        __threadfence();
        unsigned int v = atomicAdd(&g_cnt, 1u);
        s_last = (v == (unsigned)(NB - 1));
    }
    __syncthreads();

    // ---- last block: fixed-order final reduction ----
    if (s_last) {
        float f1 = 0.f, f2 = 0.f, f3 = 0.f, f4 = 0.f;
        if (t < NN) {
            float4 v = g_part[t];
            f1 = v.x; f2 = v.y; f3 = v.z; f4 = v.w;
        }
        #pragma unroll
        for (int o = 16; o > 0; o >>= 1) {
            f1 += __shfl_down_sync(0xffffffffu, f1, o);
            f2 += __shfl_down_sync(0xffffffffu, f2, o);
            f3 += __shfl_down_sync(0xffffffffu, f3, o);
            f4 += __shfl_down_sync(0xffffffffu, f4, o);
        }
        __syncthreads();
        if (l == 0 && w < 8) {
            s_red[0][w] = f1; s_red[1][w] = f2;
            s_red[2][w] = f3; s_red[3][w] = f4;
        }
        __syncthreads();
        if (t == 0) {
            float t1 = 0.f, t2 = 0.f, t3 = 0.f, t4 = 0.f;
            #pragma unroll
            for (int i = 0; i < 8; ++i) {
                t1 += s_red[0][i]; t2 += s_red[1][i];
                t3 += s_red[2][i]; t4 += s_red[3][i];
            }
            float loss1 = (t1 / fmaxf(t2 * 2.0f, 1.0f)) * 0.5f;  // * (1 - KEY_W)
            float loss2 = (t3 / fmaxf(t4 * 2.0f, 1.0f)) * 0.5f;  // * KEY_W
            out[0] = loss1 + loss2;
            g_cnt = 0;   // reset for next graph replay
        }
    }
}

extern "C" void kernel_launch(void* const* d_in, const int* in_sizes, int n_in,
                              void* d_out, int out_size)
{
    const float* pred_c = (const float*)d_in[0];
    const float* pred_o = (const float*)d_in[1];
    const float* gt_c   = (const float*)d_in[2];
    const float* gt_k   = (const float*)d_in[3];
    const int*   gt_m   = (const int*)d_in[4];

    dm_fused<<<NB, TPB>>>(pred_c, pred_o, gt_c, gt_k, gt_m, (float*)d_out);
}

// round 5
// speedup vs baseline: 1.0713x; 1.0713x over previous
#include <cuda_runtime.h>

#define NN 256      // batch
#define PP 128      // points per polygon (= segments)
#define TPB 512
#define NB  NN      // one row per block

__device__ float4 g_part[NN];
__device__ unsigned int g_cnt = 0;

__device__ __forceinline__ float smooth_l1(float p, float t) {
    float d = fabsf(p - t);
    return d < 0.25f ? 2.0f * d * d : d - 0.125f;   // BETA = 0.25
}

__global__ __launch_bounds__(TPB) void dm_fused(
    const float* __restrict__ pred_c,
    const float* __restrict__ pred_o,
    const float* __restrict__ gt_c,
    const float* __restrict__ gt_k,
    const int*   __restrict__ gt_m,
    float*       __restrict__ out)
{
    // segment tables: A=(e0,f0,g0,g1), B=(de,df,g2,-0.5/g2)
    // score(pred, k) = alpha + beta*k + gamma*k^2 (convex) -> closed-form k*
    __shared__ float4 s_tA[PP], s_tB[PP];
    __shared__ float4 s_pt[PP];                 // pred score table (-2px,-2py,|p|^2,0)
    __shared__ float2 s_pred[PP], s_po[PP], s_gt[PP], s_gk[PP];
    __shared__ int    s_mk[PP];
    __shared__ float  s_red[4][16];
    __shared__ int    s_last;

    const int n = blockIdx.x;
    const int t = threadIdx.x;
    const int p = t >> 2;           // point id 0..127
    const int h = t & 3;            // interleaved chunk 0..3

    // ---- load: all 512 threads, one element each ----
    {
        const int q = t & (PP - 1);
        const int a = t >> 7;       // constant per 4-warp group
        const size_t off = (size_t)n * PP + q;
        if (a == 0)      s_pred[q] = reinterpret_cast<const float2*>(pred_c)[off];
        else if (a == 1) s_po[q]   = reinterpret_cast<const float2*>(pred_o)[off];
        else if (a == 2) s_gt[q]   = reinterpret_cast<const float2*>(gt_c)[off];
        else             s_gk[q]   = reinterpret_cast<const float2*>(gt_k)[off];
        if (a == 0) s_mk[q] = gt_m[off];
    }
    __syncthreads();

    // ---- tables: 128 threads (1 warp-group) ----
    if (t < PP) {
        float2 a = s_gt[t];
        float2 b = s_gt[(t + PP - 1) & (PP - 1)];     // k=0 target is b
        float dx = (a.x - b.x) * 0.1f;
        float dy = (a.y - b.y) * 0.1f;
        float g2 = dx * dx + dy * dy;
        float inv = (g2 > 0.0f) ? (-0.5f / g2) : 0.0f;
        s_tA[t] = make_float4(-2.0f * b.x, -2.0f * b.y,
                              b.x * b.x + b.y * b.y,
                              2.0f * (b.x * dx + b.y * dy));
        s_tB[t] = make_float4(-2.0f * dx, -2.0f * dy, g2, inv);
        float2 pr = s_pred[t];
        s_pt[t] = make_float4(-2.0f * pr.x, -2.0f * pr.y,
                              pr.x * pr.x + pr.y * pr.y, 0.0f);
    }
    __syncthreads();

    // ---- item 1: segs sg = 4*j + h, j = 0..31, closed-form best k ----
    const float px = s_pred[p].x, py = s_pred[p].y;
    float bs1, bi1;
    {
        float val[8]; float bif[8];
        #pragma unroll
        for (int u = 0; u < 8; ++u) { val[u] = 3.4e38f; bif[u] = 0.0f; }
        #pragma unroll
        for (int j = 0; j < 32; j += 8) {
            #pragma unroll
            for (int u = 0; u < 8; ++u) {
                const int sg = 4 * (j + u) + h;
                float4 A = s_tA[sg];
                float4 B = s_tB[sg];
                float alpha = fmaf(px, A.x, fmaf(py, A.y, A.z));
                float beta  = fmaf(px, B.x, fmaf(py, B.y, A.w));
                float kf = beta * B.w;                      // vertex
                kf = fminf(fmaxf(kf, 0.0f), 9.0f);
                kf = rintf(kf);
                float v = fmaf(kf, fmaf(kf, B.z, beta), alpha);
                float bi = kf + (float)(16 * sg);           // packed 16*sg + k
                if (v < val[u]) { val[u] = v; bif[u] = bi; }
            }
        }
        bs1 = val[0]; bi1 = bif[0];
        #pragma unroll
        for (int u = 1; u < 8; ++u)
            if (val[u] < bs1 || (val[u] == bs1 && bif[u] < bi1)) { bs1 = val[u]; bi1 = bif[u]; }
        // combine across the 4 chunks (adjacent lanes) — exact tie-break on index
        #pragma unroll
        for (int o = 1; o <= 2; o <<= 1) {
            float os = __shfl_xor_sync(0xffffffffu, bs1, o);
            float ob = __shfl_xor_sync(0xffffffffu, bi1, o);
            if (os < bs1 || (os == bs1 && ob < bi1)) { bs1 = os; bi1 = ob; }
        }
    }

    // ---- item 2: preds pj = 4*j + h for key point p ----
    float b2m, j2f;
    {
        const float kx = s_gk[p].x, ky = s_gk[p].y;
        float b2[4]; float j2[4];
        #pragma unroll
        for (int u = 0; u < 4; ++u) { b2[u] = 3.4e38f; j2[u] = 0.0f; }
        #pragma unroll
        for (int j = 0; j < 32; j += 4) {
            #pragma unroll
            for (int u = 0; u < 4; ++u) {
                const int pj = 4 * (j + u) + h;
                float4 E = s_pt[pj];
                float d = fmaf(kx, E.x, fmaf(ky, E.y, E.z));
                if (d < b2[u]) { b2[u] = d; j2[u] = (float)pj; }
            }
        }
        b2m = b2[0]; j2f = j2[0];
        #pragma unroll
        for (int u = 1; u < 4; ++u)
            if (b2[u] < b2m || (b2[u] == b2m && j2[u] < j2f)) { b2m = b2[u]; j2f = j2[u]; }
        #pragma unroll
        for (int o = 1; o <= 2; o <<= 1) {
            float os = __shfl_xor_sync(0xffffffffu, b2m, o);
            float oj = __shfl_xor_sync(0xffffffffu, j2f, o);
            if (os < b2m || (os == b2m && oj < j2f)) { b2m = os; j2f = oj; }
        }
    }

    // ---- per-point losses: one lane per pred (h == 0) ----
    float s1 = 0.0f, c1 = 0.0f, s2 = 0.0f, c2 = 0.0f;
    if (h == 0) {
        // item 1
        {
            int bi = (int)bi1;
            int sg = bi >> 4;
            float kf = (float)(bi & 15);
            float4 A = s_tA[sg];
            float4 B = s_tB[sg];
            float tx = -0.5f * fmaf(kf, B.x, A.x);
            float ty = -0.5f * fmaf(kf, B.y, A.y);
            float dxx = px - tx, dyy = py - ty;
            float d2 = dxx * dxx + dyy * dyy;
            if (d2 <= 1.0e6f) {
                float2 mo = s_po[p];
                float ox = (tx - px) * 0.25f;
                float oy = (ty - py) * 0.25f;
                s1 = smooth_l1(mo.x, ox) + smooth_l1(mo.y, oy);
                c1 = 1.0f;
            }
        }
        // item 2
        {
            float2 kk = s_gk[p];
            float kk2 = kk.x * kk.x + kk.y * kk.y;          // restore dist^2
            if (s_mk[p] && (b2m + kk2) <= 1.0e6f) {
                int j2m = (int)j2f;
                float2 pg = s_pred[j2m];
                float2 og = s_po[j2m];
                float ox = (kk.x - pg.x) * 0.25f;
                float oy = (kk.y - pg.y) * 0.25f;
                s2 = smooth_l1(og.x, ox) + smooth_l1(og.y, oy);
                c2 = 1.0f;
            }
        }
    }

    // ---- deterministic block reduction over all 16 warps ----
    #pragma unroll
    for (int o = 16; o > 0; o >>= 1) {
        s1 += __shfl_down_sync(0xffffffffu, s1, o);
        c1 += __shfl_down_sync(0xffffffffu, c1, o);
        s2 += __shfl_down_sync(0xffffffffu, s2, o);
        c2 += __shfl_down_sync(0xffffffffu, c2, o);
    }
    const int w = t >> 5, l = t & 31;
    if (l == 0) {
        s_red[0][w] = s1; s_red[1][w] = c1;
        s_red[2][w] = s2; s_red[3][w] = c2;
    }
    __syncthreads();
    if (t == 0) {
        float a0 = 0.f, a1 = 0.f, a2 = 0.f, a3 = 0.f;
        #pragma unroll
        for (int i = 0; i < 16; ++i) {
            a0 += s_red[0][i]; a1 += s_red[1][i];
            a2 += s_red[2][i]; a3 += s_red[3][i];
        }
        g_part[n] = make_float4(a0, a1, a2, a3);
        __threadfence();
        unsigned int v = atomicAdd(&g_cnt, 1u);
        s_last = (v == (unsigned)(NB - 1));
    }
    __syncthreads();

    // ---- last block: fixed-order final reduction (bitwise deterministic) ----
    if (s_last) {
        float f1 = 0.f, f2 = 0.f, f3 = 0.f, f4 = 0.f;
        if (t < NN) {
            float4 v = g_part[t];
            f1 = v.x; f2 = v.y; f3 = v.z; f4 = v.w;
        }
        #pragma unroll
        for (int o = 16; o > 0; o >>= 1) {
            f1 += __shfl_down_sync(0xffffffffu, f1, o);
            f2 += __shfl_down_sync(0xffffffffu, f2, o);
            f3 += __shfl_down_sync(0xffffffffu, f3, o);
            f4 += __shfl_down_sync(0xffffffffu, f4, o);
        }
        __syncthreads();
        if (l == 0) {
            s_red[0][w] = f1; s_red[1][w] = f2;
            s_red[2][w] = f3; s_red[3][w] = f4;
        }
        __syncthreads();
        if (t == 0) {
            float t1 = 0.f, t2 = 0.f, t3 = 0.f, t4 = 0.f;
            #pragma unroll
            for (int i = 0; i < 16; ++i) {
                t1 += s_red[0][i]; t2 += s_red[1][i];
                t3 += s_red[2][i]; t4 += s_red[3][i];
            }
            float loss1 = (t1 / fmaxf(t2 * 2.0f, 1.0f)) * 0.5f;  // * (1 - KEY_W)
            float loss2 = (t3 / fmaxf(t4 * 2.0f, 1.0f)) * 0.5f;  // * KEY_W
            out[0] = loss1 + loss2;
            g_cnt = 0;   // reset for next graph replay
        }
    }
}

extern "C" void kernel_launch(void* const* d_in, const int* in_sizes, int n_in,
                              void* d_out, int out_size)
{
    const float* pred_c = (const float*)d_in[0];
    const float* pred_o = (const float*)d_in[1];
    const float* gt_c   = (const float*)d_in[2];
    const float* gt_k   = (const float*)d_in[3];
    const int*   gt_m   = (const int*)d_in[4];

    dm_fused<<<NB, TPB>>>(pred_c, pred_o, gt_c, gt_k, gt_m, (float*)d_out);
}

// round 6
// speedup vs baseline: 1.1679x; 1.0902x over previous
#include <cuda_runtime.h>

#define NN 256      // batch
#define PP 128      // points per polygon (= segments)
#define TPB 512
#define NB  NN
#define SCH (PP / 4)      // 32 segments per h-chunk
#define PCH (PP / 4)      // 32 preds per h-chunk

__device__ float4 g_part[NN];
__device__ unsigned int g_cnt = 0;

__device__ __forceinline__ float smooth_l1(float p, float t) {
    float d = fabsf(p - t);
    return d < 0.25f ? 2.0f * d * d : d - 0.125f;   // BETA = 0.25
}

__global__ void __launch_bounds__(TPB, 3) dm_fused(
    const float* __restrict__ pred_c,
    const float* __restrict__ pred_o,
    const float* __restrict__ gt_c,
    const float* __restrict__ gt_k,
    const int*   __restrict__ gt_m,
    float*       __restrict__ out)
{
    // segment tables: A=(e0,f0,g0,g1), B=(de,df,g2,-0.5/g2)
    // score(pred,k) = alpha + beta*k + gamma*k^2 (convex) -> closed-form k*
    __shared__ float4 s_tA[PP], s_tB[PP];
    __shared__ float4 s_pt[PP];                 // pred score table (-2px,-2py,|p|^2,0)
    __shared__ float2 s_pred[PP], s_po[PP], s_gt[PP], s_gk[PP];
    __shared__ float  s_bs[4 * PP];
    __shared__ float  s_bi[4 * PP];             // packed float index 16*sg + k
    __shared__ float  s_b2[4 * PP];
    __shared__ int    s_j2[4 * PP];
    __shared__ float  s_red[4][16];
    __shared__ int    s_last;

    const int n = blockIdx.x;
    const int t = threadIdx.x;
    const int p = t & (PP - 1);
    const int h = t >> 7;           // chunk 0..3 (uniform within warp -> broadcast LDS)

    if (t < PP) {
        const float2* pc2 = reinterpret_cast<const float2*>(pred_c) + (size_t)n * PP;
        const float2* po2 = reinterpret_cast<const float2*>(pred_o) + (size_t)n * PP;
        const float2* gc2 = reinterpret_cast<const float2*>(gt_c)   + (size_t)n * PP;
        const float2* gk2 = reinterpret_cast<const float2*>(gt_k)   + (size_t)n * PP;
        s_pred[t] = pc2[t];
        s_po[t]   = po2[t];
        s_gt[t]   = gc2[t];
        s_gk[t]   = gk2[t];
    }
    __syncthreads();

    if (t < PP) {
        float2 a = s_gt[t];
        float2 b = s_gt[(t + PP - 1) & (PP - 1)];     // k=0 target is b
        float dx = (a.x - b.x) * 0.1f;
        float dy = (a.y - b.y) * 0.1f;
        float g2 = dx * dx + dy * dy;
        float inv = (g2 > 0.0f) ? (-0.5f / g2) : 0.0f;
        s_tA[t] = make_float4(-2.0f * b.x, -2.0f * b.y,
                              b.x * b.x + b.y * b.y,
                              2.0f * (b.x * dx + b.y * dy));
        s_tB[t] = make_float4(-2.0f * dx, -2.0f * dy, g2, inv);
        float2 pr = s_pred[t];
        s_pt[t] = make_float4(-2.0f * pr.x, -2.0f * pr.y,
                              pr.x * pr.x + pr.y * pr.y, 0.0f);
    }
    __syncthreads();

    // ---- item 1: chunk h of segments, closed-form best k per segment ----
    const float px = s_pred[p].x, py = s_pred[p].y;
    {
        const int   base = h * SCH;
        const float fb   = (float)(h * 512);      // 16 * base, hoisted (single I2F)
        float val[4]; float bif[4];
        #pragma unroll
        for (int u = 0; u < 4; ++u) { val[u] = 3.4e38f; bif[u] = 0.0f; }
        #pragma unroll
        for (int j = 0; j < SCH; j += 4) {
            #pragma unroll
            for (int u = 0; u < 4; ++u) {
                const int sg = base + j + u;
                float4 A = s_tA[sg];
                float4 B = s_tB[sg];
                float alpha = fmaf(px, A.x, fmaf(py, A.y, A.z));
                float beta  = fmaf(px, B.x, fmaf(py, B.y, A.w));
                float kf = beta * B.w;                      // vertex
                kf = fminf(fmaxf(kf, 0.0f), 9.0f);
                kf = rintf(kf);
                float v = fmaf(kf, fmaf(kf, B.z, beta), alpha);
                // packed index 16*sg + k, all-float: imm fold + hoisted fb
                float bi = (kf + (float)(16 * (j + u))) + fb;
                if (v < val[u]) { val[u] = v; bif[u] = bi; }
            }
        }
        float bs = val[0]; float bi = bif[0];
        #pragma unroll
        for (int u = 1; u < 4; ++u)
            if (val[u] < bs || (val[u] == bs && bif[u] < bi)) { bs = val[u]; bi = bif[u]; }
        s_bs[t] = bs; s_bi[t] = bi;
    }

    // ---- item 2: chunk h of preds for key point p (score form) ----
    {
        const float kx = s_gk[p].x, ky = s_gk[p].y;
        const int pb = h * PCH;
        float b2[4]; int j2[4];
        #pragma unroll
        for (int u = 0; u < 4; ++u) { b2[u] = 3.4e38f; j2[u] = 0; }
        #pragma unroll
        for (int j = 0; j < PCH; j += 4) {
            #pragma unroll
            for (int u = 0; u < 4; ++u) {
                float4 E = s_pt[pb + j + u];
                float d = fmaf(kx, E.x, fmaf(ky, E.y, E.z));
                if (d < b2[u]) { b2[u] = d; j2[u] = pb + j + u; }
            }
        }
        float bs = b2[0]; int bi = j2[0];
        #pragma unroll
        for (int u = 1; u < 4; ++u)
            if (b2[u] < bs || (b2[u] == bs && j2[u] < bi)) { bs = b2[u]; bi = j2[u]; }
        s_b2[t] = bs; s_j2[t] = bi;
    }
    __syncthreads();

    // ---- combine across h-chunks + per-point losses (t < 128) ----
    float s1 = 0.0f, c1 = 0.0f, s2 = 0.0f, c2 = 0.0f;
    if (t < PP) {
        // item 1
        float bs = s_bs[t]; float bif = s_bi[t];
        #pragma unroll
        for (int hh = 1; hh < 4; ++hh) {
            float s = s_bs[hh * PP + t]; float b = s_bi[hh * PP + t];
            if (s < bs || (s == bs && b < bif)) { bs = s; bif = b; }
        }
        {
            int bi = (int)bif;
            int sg = bi >> 4;
            float kf = (float)(bi & 15);
            float4 A = s_tA[sg];
            float4 B = s_tB[sg];
            float tx = -0.5f * fmaf(kf, B.x, A.x);
            float ty = -0.5f * fmaf(kf, B.y, A.y);
            float mpx = s_pred[t].x, mpy = s_pred[t].y;
            float dxx = mpx - tx, dyy = mpy - ty;
            float d2 = dxx * dxx + dyy * dyy;
            if (d2 <= 1.0e6f) {
                float2 mo = s_po[t];
                float ox = (tx - mpx) * 0.25f;
                float oy = (ty - mpy) * 0.25f;
                s1 = smooth_l1(mo.x, ox) + smooth_l1(mo.y, oy);
                c1 = 1.0f;
            }
        }
        // item 2
        float b2m = s_b2[t]; int j2m = s_j2[t];
        #pragma unroll
        for (int hh = 1; hh < 4; ++hh) {
            float s = s_b2[hh * PP + t]; int j = s_j2[hh * PP + t];
            if (s < b2m || (s == b2m && j < j2m)) { b2m = s; j2m = j; }
        }
        int mk = gt_m[(size_t)n * PP + t];
        float2 kk = s_gk[t];
        float kk2 = kk.x * kk.x + kk.y * kk.y;              // restore dist^2
        if (mk && (b2m + kk2) <= 1.0e6f) {
            float2 pg = s_pred[j2m];
            float2 og = s_po[j2m];
            float ox = (kk.x - pg.x) * 0.25f;
            float oy = (kk.y - pg.y) * 0.25f;
            s2 = smooth_l1(og.x, ox) + smooth_l1(og.y, oy);
            c2 = 1.0f;
        }
    }

    // ---- deterministic block reduction over all 16 warps ----
    #pragma unroll
    for (int o = 16; o > 0; o >>= 1) {
        s1 += __shfl_down_sync(0xffffffffu, s1, o);
        c1 += __shfl_down_sync(0xffffffffu, c1, o);
        s2 += __shfl_down_sync(0xffffffffu, s2, o);
        c2 += __shfl_down_sync(0xffffffffu, c2, o);
    }
    const int w = t >> 5, l = t & 31;
    if (l == 0) {
        s_red[0][w] = s1; s_red[1][w] = c1;
        s_red[2][w] = s2; s_red[3][w] = c2;
    }
    __syncthreads();
    if (t == 0) {
        float a0 = 0.f, a1 = 0.f, a2 = 0.f, a3 = 0.f;
        #pragma unroll
        for (int i = 0; i < 16; ++i) {
            a0 += s_red[0][i]; a1 += s_red[1][i];
            a2 += s_red[2][i]; a3 += s_red[3][i];
        }
        g_part[n] = make_float4(a0, a1, a2, a3);
        __threadfence();
        unsigned int v = atomicAdd(&g_cnt, 1u);
        s_last = (v == (unsigned)(NB - 1));
    }
    __syncthreads();

    // ---- last block: fixed-order final reduction (bitwise deterministic) ----
    if (s_last) {
        float f1 = 0.f, f2 = 0.f, f3 = 0.f, f4 = 0.f;
        if (t < NN) {
            float4 v = g_part[t];
            f1 = v.x; f2 = v.y; f3 = v.z; f4 = v.w;
        }
        #pragma unroll
        for (int o = 16; o > 0; o >>= 1) {
            f1 += __shfl_down_sync(0xffffffffu, f1, o);
            f2 += __shfl_down_sync(0xffffffffu, f2, o);
            f3 += __shfl_down_sync(0xffffffffu, f3, o);
            f4 += __shfl_down_sync(0xffffffffu, f4, o);
        }
        __syncthreads();
        if (l == 0) {
            s_red[0][w] = f1; s_red[1][w] = f2;
            s_red[2][w] = f3; s_red[3][w] = f4;
        }
        __syncthreads();
        if (t == 0) {
            float t1 = 0.f, t2 = 0.f, t3 = 0.f, t4 = 0.f;
            #pragma unroll
            for (int i = 0; i < 16; ++i) {
                t1 += s_red[0][i]; t2 += s_red[1][i];
                t3 += s_red[2][i]; t4 += s_red[3][i];
            }
            float loss1 = (t1 / fmaxf(t2 * 2.0f, 1.0f)) * 0.5f;  // * (1 - KEY_W)
            float loss2 = (t3 / fmaxf(t4 * 2.0f, 1.0f)) * 0.5f;  // * KEY_W
            out[0] = loss1 + loss2;
            g_cnt = 0;   // reset for next graph replay
        }
    }
}

extern "C" void kernel_launch(void* const* d_in, const int* in_sizes, int n_in,
                              void* d_out, int out_size)
{
    const float* pred_c = (const float*)d_in[0];
    const float* pred_o = (const float*)d_in[1];
    const float* gt_c   = (const float*)d_in[2];
    const float* gt_k   = (const float*)d_in[3];
    const int*   gt_m   = (const int*)d_in[4];

    dm_fused<<<NB, TPB>>>(pred_c, pred_o, gt_c, gt_k, gt_m, (float*)d_out);
}